// round 3
// baseline (speedup 1.0000x reference)
#include <cuda_runtime.h>
#include <cuda_bf16.h>
#include <math.h>

// Problem dims
#define BB 16
#define SS 100
#define LL 100          // MAX_CODE_LEN
#define FEAT 20         // INPUT_DIM
#define EMB 100
#define DD 320          // D = 20 + 3*100
#define RNNIN 340       // 2*20 + 3*100
#define HID 128
#define G4 512
#define NOUT 10

#define NROWS (BB*SS*LL)       // 160000
#define K1_ROWS 128
#define K1_GRID (NROWS / K1_ROWS)  // 1250
#define AS_STRIDE 321

// -------- scratch (device globals; no allocation allowed) --------
static __device__ float g_cw[BB*LL*SS];        // [b][l][s]
static __device__ float g_aw[BB*SS*LL];        // [b][s][l]
static __device__ float g_rnn[BB*SS*RNNIN];    // [b][s][340]
static __device__ float g_gx[BB*SS*G4];        // x-part gates [b][s][512]
static __device__ float g_hs[BB*SS*HID];       // lstm outputs
static __device__ float g_WihT[RNNIN*G4];      // [k][n]
static __device__ float g_WhhT[HID*G4];        // [k][n]

__device__ __forceinline__ float sigf(float x) { return 1.0f / (1.0f + expf(-x)); }

// ----------------------------------------------------------------
// K0: transpose W_ih and W_hh for coalesced column access
// ----------------------------------------------------------------
__global__ void k0_transpose(const float* __restrict__ Wih, const float* __restrict__ Whh) {
    int t = blockIdx.x * blockDim.x + threadIdx.x;
    if (t < RNNIN * G4) {          // Wih is [512][340]
        int n = t / RNNIN, k = t % RNNIN;
        g_WihT[k * G4 + n] = Wih[t];
    }
    if (t < HID * G4) {            // Whh is [512][128]
        int n = t / HID, k = t % HID;
        g_WhhT[k * G4 + n] = Whh[t];
    }
}

// ----------------------------------------------------------------
// K1: fused gather + (full @ W_trans^T) + tanh + dot(W_attn) -> cw
// One CTA = 128 context rows. A tile gathered once into smem.
// ----------------------------------------------------------------
__global__ void __launch_bounds__(256, 1)
k1_context(const float* __restrict__ x,
           const float* __restrict__ etab_n,
           const float* __restrict__ etab_p,
           const float* __restrict__ Wt,
           const float* __restrict__ bt,
           const float* __restrict__ Wa,
           const float* __restrict__ ba)
{
    extern __shared__ float sm[];
    float* A_s = sm;                         // 128 * 321
    float* W_s = sm + K1_ROWS * AS_STRIDE;   // 32 * 68
    int*   si  = (int*)(W_s + 32 * 68);      // 128
    int*   ei  = si + K1_ROWS;
    int*   pi  = ei + K1_ROWS;

    const int t = threadIdx.x;
    const int r0blk = blockIdx.x * K1_ROWS;

    // decode indices for the 128 rows
    if (t < K1_ROWS) {
        int r  = r0blk + t;
        int bs = r / LL;
        int l  = r % LL;
        int xb = bs * DD + FEAT + 3 * l;
        si[t] = (int)x[xb];
        pi[t] = (int)x[xb + 1];
        ei[t] = (int)x[xb + 2];
    }
    __syncthreads();

    // gather A tile: A_s[rl][k], k in [0,320)
    for (int e = t; e < K1_ROWS * DD; e += 256) {
        int rl = e / DD;
        int k  = e % DD;
        float v;
        if (k < EMB)            v = etab_n[si[rl] * EMB + k];
        else if (k < 2 * EMB)   v = etab_n[ei[rl] * EMB + (k - EMB)];
        else if (k < 3 * EMB)   v = etab_p[pi[rl] * EMB + (k - 2 * EMB)];
        else {
            int bs = (r0blk + rl) / LL;
            v = x[bs * DD + (k - 3 * EMB)];
        }
        A_s[rl * AS_STRIDE + k] = v;
    }

    const int tx = t & 15;        // d group (16 x 4 = 64 cols)
    const int ty = t >> 4;        // r group (16 x 8 = 128 rows)
    const int r0 = ty * 8;
    const int d0 = tx * 4;

    float rowsum[8];
#pragma unroll
    for (int i = 0; i < 8; i++) rowsum[i] = 0.f;

    for (int db = 0; db < 5; db++) {
        const int dbase = db * 64;
        float acc[8][4];
#pragma unroll
        for (int i = 0; i < 8; i++)
#pragma unroll
            for (int j = 0; j < 4; j++) acc[i][j] = 0.f;

        for (int kb = 0; kb < 10; kb++) {
            const int kbase = kb * 32;
            __syncthreads();
            // load W chunk (64 d x 32 k) transposed into W_s[k][d]
            for (int e = t; e < 64 * 32; e += 256) {
                int dl = e >> 5, kl = e & 31;
                W_s[kl * 68 + dl] = Wt[(dbase + dl) * DD + kbase + kl];
            }
            __syncthreads();
#pragma unroll
            for (int kl = 0; kl < 32; kl++) {
                float4 wv = *(const float4*)&W_s[kl * 68 + d0];
                const float* ap = &A_s[r0 * AS_STRIDE + kbase + kl];
#pragma unroll
                for (int i = 0; i < 8; i++) {
                    float a = ap[i * AS_STRIDE];
                    acc[i][0] += a * wv.x;
                    acc[i][1] += a * wv.y;
                    acc[i][2] += a * wv.z;
                    acc[i][3] += a * wv.w;
                }
            }
        }
        // epilogue: tanh + attn dot
        float btv[4], wav[4];
#pragma unroll
        for (int j = 0; j < 4; j++) {
            btv[j] = bt[dbase + d0 + j];
            wav[j] = Wa[dbase + d0 + j];
        }
#pragma unroll
        for (int i = 0; i < 8; i++) {
#pragma unroll
            for (int j = 0; j < 4; j++)
                rowsum[i] += tanhf(acc[i][j] + btv[j]) * wav[j];
        }
    }

    // reduce across the 16 tx lanes; reuse A_s
    __syncthreads();
    float* red = A_s;
#pragma unroll
    for (int i = 0; i < 8; i++) red[(r0 + i) * 16 + tx] = rowsum[i];
    __syncthreads();
    if (t < K1_ROWS) {
        float tot = 0.f;
#pragma unroll
        for (int j = 0; j < 16; j++) tot += red[t * 16 + j];
        tot += ba[0];
        int r  = r0blk + t;
        int bs = r / LL;
        int l  = r % LL;
        int b  = bs / SS;
        int s  = bs % SS;
        g_cw[(b * LL + l) * SS + s] = tot;
    }
}

// ----------------------------------------------------------------
// K2: softmax over s (axis=1) for each (b,l); write aw in [b][s][l]
// ----------------------------------------------------------------
__global__ void k2_softmax() {
    const int bl = blockIdx.x;     // b*100 + l
    const int t  = threadIdx.x;    // 128 threads
    const float* row = g_cw + bl * SS;
    float v0 = (t < SS) ? row[t] : -3.0e38f;

    __shared__ float sw[4];
    float v = v0;
#pragma unroll
    for (int off = 16; off; off >>= 1) v = fmaxf(v, __shfl_xor_sync(~0u, v, off));
    if ((t & 31) == 0) sw[t >> 5] = v;
    __syncthreads();
    float mx = fmaxf(fmaxf(sw[0], sw[1]), fmaxf(sw[2], sw[3]));
    __syncthreads();

    float e = (t < SS) ? expf(v0 - mx) : 0.f;
    float sv = e;
#pragma unroll
    for (int off = 16; off; off >>= 1) sv += __shfl_xor_sync(~0u, sv, off);
    if ((t & 31) == 0) sw[t >> 5] = sv;
    __syncthreads();
    float tot = sw[0] + sw[1] + sw[2] + sw[3];

    if (t < SS) {
        int b = bl / LL, l = bl % LL;
        g_aw[(b * SS + t) * LL + l] = e / tot;   // s = t
    }
}

// ----------------------------------------------------------------
// K3: code_vec via re-gather; build rnn_in = [feat(20), code_vec(320)]
// ----------------------------------------------------------------
__global__ void k3_codevec(const float* __restrict__ x,
                           const float* __restrict__ etab_n,
                           const float* __restrict__ etab_p)
{
    __shared__ float aw_s[LL];
    __shared__ int si[LL], pi[LL], ei[LL];
    __shared__ float awsum_s;
    const int bs = blockIdx.x;
    const int t  = threadIdx.x;   // 128

    if (t < LL) {
        aw_s[t] = g_aw[bs * LL + t];
        int xb = bs * DD + FEAT + 3 * t;
        si[t] = (int)x[xb];
        pi[t] = (int)x[xb + 1];
        ei[t] = (int)x[xb + 2];
    }
    __syncthreads();
    if (t == 0) {
        float a = 0.f;
        for (int l = 0; l < LL; l++) a += aw_s[l];
        awsum_s = a;
    }
    __syncthreads();

    float* outrow = g_rnn + bs * RNNIN;
    for (int j = t; j < RNNIN; j += 128) {
        float v;
        if (j < FEAT) {
            v = x[bs * DD + j];
        } else {
            int k = j - FEAT;
            float acc = 0.f;
            if (k < EMB) {
                for (int l = 0; l < LL; l++) acc += etab_n[si[l] * EMB + k] * aw_s[l];
            } else if (k < 2 * EMB) {
                int km = k - EMB;
                for (int l = 0; l < LL; l++) acc += etab_n[ei[l] * EMB + km] * aw_s[l];
            } else if (k < 3 * EMB) {
                int km = k - 2 * EMB;
                for (int l = 0; l < LL; l++) acc += etab_p[pi[l] * EMB + km] * aw_s[l];
            } else {
                acc = x[bs * DD + (k - 3 * EMB)] * awsum_s;
            }
            v = acc;
        }
        outrow[j] = v;
    }
}

// ----------------------------------------------------------------
// K4: x-part gates: g_gx = rnn_in @ W_ih^T + b_ih + b_hh
// CTA = 16 rows x 512 cols
// ----------------------------------------------------------------
__global__ void __launch_bounds__(512)
k4_gates(const float* __restrict__ bih, const float* __restrict__ bhh)
{
    __shared__ float A_s[16 * RNNIN];
    const int n  = threadIdx.x;        // gate column
    const int r0 = blockIdx.x * 16;

    for (int e = n; e < 16 * RNNIN; e += 512)
        A_s[e] = g_rnn[r0 * RNNIN + e];
    __syncthreads();

    float acc[16];
#pragma unroll
    for (int i = 0; i < 16; i++) acc[i] = 0.f;

#pragma unroll 4
    for (int k = 0; k < RNNIN; k++) {
        float w = g_WihT[k * G4 + n];
#pragma unroll
        for (int i = 0; i < 16; i++)
            acc[i] += A_s[i * RNNIN + k] * w;
    }
    float bias = bih[n] + bhh[n];
#pragma unroll
    for (int i = 0; i < 16; i++)
        g_gx[(r0 + i) * G4 + n] = acc[i] + bias;
}

// ----------------------------------------------------------------
// K5: LSTM recurrence. One CTA per batch element, 512 threads.
// ----------------------------------------------------------------
__global__ void __launch_bounds__(512)
k5_lstm()
{
    __shared__ float h_s[HID];
    __shared__ float gs[G4];
    const int b = blockIdx.x;
    const int n = threadIdx.x;

    if (n < HID) h_s[n] = 0.f;
    float c = 0.f;
    __syncthreads();

    for (int s = 0; s < SS; s++) {
        float acc = g_gx[(b * SS + s) * G4 + n];
#pragma unroll 16
        for (int k = 0; k < HID; k++)
            acc += g_WhhT[k * G4 + n] * h_s[k];
        gs[n] = acc;
        __syncthreads();
        if (n < HID) {
            float gi = gs[n];
            float gf = gs[HID + n];
            float gg = gs[2 * HID + n];
            float go = gs[3 * HID + n];
            c = sigf(gf) * c + sigf(gi) * tanhf(gg);
            float h = sigf(go) * tanhf(c);
            h_s[n] = h;
            g_hs[(b * SS + s) * HID + n] = h;
        }
        __syncthreads();
    }
}

// ----------------------------------------------------------------
// K6: out = sigmoid(hs @ W_fc^T + b_fc)
// ----------------------------------------------------------------
__global__ void k6_fc(const float* __restrict__ Wfc,
                      const float* __restrict__ bfc,
                      float* __restrict__ out)
{
    int t = blockIdx.x * blockDim.x + threadIdx.x;
    if (t >= BB * SS * NOUT) return;
    int bs = t / NOUT;
    int o  = t % NOUT;
    const float* hrow = g_hs + bs * HID;
    const float* wrow = Wfc + o * HID;
    float acc = bfc[o];
#pragma unroll 8
    for (int u = 0; u < HID; u++) acc += hrow[u] * wrow[u];
    out[t] = sigf(acc);
}

// ----------------------------------------------------------------
extern "C" void kernel_launch(void* const* d_in, const int* in_sizes, int n_in,
                              void* d_out, int out_size)
{
    const float* x      = (const float*)d_in[0];
    const float* etab_n = (const float*)d_in[1];
    const float* etab_p = (const float*)d_in[2];
    const float* Wt     = (const float*)d_in[3];
    const float* bt     = (const float*)d_in[4];
    const float* Wa     = (const float*)d_in[5];
    const float* ba     = (const float*)d_in[6];
    const float* Wih    = (const float*)d_in[7];
    const float* Whh    = (const float*)d_in[8];
    const float* bih    = (const float*)d_in[9];
    const float* bhh    = (const float*)d_in[10];
    const float* Wfc    = (const float*)d_in[11];
    const float* bfc    = (const float*)d_in[12];
    float* out = (float*)d_out;

    const int k1_smem = (K1_ROWS * AS_STRIDE + 32 * 68) * 4 + 3 * K1_ROWS * 4;
    cudaFuncSetAttribute(k1_context, cudaFuncAttributeMaxDynamicSharedMemorySize, k1_smem);

    // transpose recurrent / input weights
    {
        int total = RNNIN * G4;
        k0_transpose<<<(total + 255) / 256, 256>>>(Wih, Whh);
    }
    k1_context<<<K1_GRID, 256, k1_smem>>>(x, etab_n, etab_p, Wt, bt, Wa, ba);
    k2_softmax<<<BB * LL, 128>>>();
    k3_codevec<<<BB * SS, 128>>>(x, etab_n, etab_p);
    k4_gates<<<BB * SS / 16, 512>>>(bih, bhh);
    k5_lstm<<<BB, 512>>>();
    {
        int total = BB * SS * NOUT;
        k6_fc<<<(total + 255) / 256, 256>>>(Wfc, bfc, out);
    }
}

// round 5
// speedup vs baseline: 2.3258x; 2.3258x over previous
#include <cuda_runtime.h>
#include <cuda_bf16.h>
#include <math.h>

// Problem dims
#define BB 16
#define SS 100
#define LL 100          // MAX_CODE_LEN
#define FEAT 20         // INPUT_DIM
#define EMB 100
#define DD 320          // D = 20 + 3*100
#define RNNIN 340       // 2*20 + 3*100
#define HID 128
#define G4 512
#define NOUT 10

#define NVOC_N 10002
#define NVOC_P 50002
#define PROJ_NODE_BLOCKS 79   // ceil(10002/128)
#define PROJ_PATH_BLOCKS 391  // ceil(50002/128)
#define WS_STRIDE 68          // multiple of 4: float4 reads stay 16B-aligned
#define AS_STRIDE 104

// -------- scratch (device globals; no allocation allowed) --------
static __device__ float g_Tn[NVOC_N * 640];    // [v][0:320]=start-slot proj, [v][320:640]=end-slot proj
static __device__ float g_Tp[NVOC_P * 320];    // path-slot proj
static __device__ float g_cw[BB*LL*SS];        // [b][l][s]
static __device__ float g_aw[BB*SS*LL];        // [b][s][l]
static __device__ float g_rnn[BB*SS*RNNIN];    // [b][s][340]
static __device__ float g_gx[BB*SS*G4];        // x-part gates [b][s][512]
static __device__ float g_hs[BB*SS*HID];       // lstm outputs
static __device__ float g_WihT[RNNIN*G4];      // [k][n]
static __device__ float g_WhhT[HID*G4];        // [k][n]

__device__ __forceinline__ float sigf(float x) { return 1.0f / (1.0f + expf(-x)); }

// ----------------------------------------------------------------
// K0: transpose W_ih and W_hh for coalesced column access
// ----------------------------------------------------------------
__global__ void k0_transpose(const float* __restrict__ Wih, const float* __restrict__ Whh) {
    int t = blockIdx.x * blockDim.x + threadIdx.x;
    if (t < RNNIN * G4) {          // Wih is [512][340]
        int n = t / RNNIN, k = t % RNNIN;
        g_WihT[k * G4 + n] = Wih[t];
    }
    if (t < HID * G4) {            // Whh is [512][128]
        int n = t / HID, k = t % HID;
        g_WhhT[k * G4 + n] = Whh[t];
    }
}

// ----------------------------------------------------------------
// KP: project embedding tables through W_trans column blocks.
//   node blocks: C[v][d]      = sum_k etab_n[v][k] * Wt[d][k]        (d in 0:320)
//                C[v][320+d]  = sum_k etab_n[v][k] * Wt[d][100+k]
//   path blocks: C[v][d]      = sum_k etab_p[v][k] * Wt[d][200+k]
// CTA = 128 vocab rows; loops over 64-wide d blocks.
// ----------------------------------------------------------------
__global__ void __launch_bounds__(256, 1)
kp_project(const float* __restrict__ etab_n,
           const float* __restrict__ etab_p,
           const float* __restrict__ Wt)
{
    extern __shared__ float sm[];
    float* A_s = sm;                        // 128 * 104
    float* W_s = sm + 128 * AS_STRIDE;      // 100 * 68

    const int t = threadIdx.x;
    const bool isnode = blockIdx.x < PROJ_NODE_BLOCKS;
    const int vb = isnode ? blockIdx.x : blockIdx.x - PROJ_NODE_BLOCKS;
    const int v0 = vb * 128;
    const int nv = isnode ? NVOC_N : NVOC_P;
    const float* tab = isnode ? etab_n : etab_p;
    float* outp = isnode ? g_Tn : g_Tp;
    const int ostride = isnode ? 640 : 320;
    const int ndb = isnode ? 10 : 5;

    // load A tile (128 x 100), zero-pad out-of-range rows
    for (int e = t; e < 128 * EMB; e += 256) {
        int r = e / EMB, k = e % EMB;
        float v = 0.f;
        if (v0 + r < nv) v = tab[(v0 + r) * EMB + k];
        A_s[r * AS_STRIDE + k] = v;
    }

    const int tx = t & 15;      // 16 x 4 = 64 cols
    const int ty = t >> 4;      // 16 x 8 = 128 rows
    const int d0 = tx * 4;
    const int r0 = ty * 8;

    for (int db = 0; db < ndb; db++) {
        const int dbase = db * 64;
        int wrow, kofs;
        if (isnode) {
            if (db < 5) { wrow = dbase;       kofs = 0;   }
            else        { wrow = dbase - 320; kofs = 100; }
        } else          { wrow = dbase;       kofs = 200; }

        __syncthreads();
        // load W chunk transposed: W_s[k][d] = Wt[(wrow+d)][kofs+k]; coalesced along k
        for (int e = t; e < 64 * EMB; e += 256) {
            int d = e / EMB, k = e % EMB;
            W_s[k * WS_STRIDE + d] = Wt[(wrow + d) * DD + kofs + k];
        }
        __syncthreads();

        float acc[8][4];
#pragma unroll
        for (int i = 0; i < 8; i++)
#pragma unroll
            for (int j = 0; j < 4; j++) acc[i][j] = 0.f;

#pragma unroll 4
        for (int k = 0; k < EMB; k++) {
            float4 wv = *(const float4*)&W_s[k * WS_STRIDE + d0];
            const float* ap = &A_s[r0 * AS_STRIDE + k];
#pragma unroll
            for (int i = 0; i < 8; i++) {
                float a = ap[i * AS_STRIDE];
                acc[i][0] += a * wv.x;
                acc[i][1] += a * wv.y;
                acc[i][2] += a * wv.z;
                acc[i][3] += a * wv.w;
            }
        }
#pragma unroll
        for (int i = 0; i < 8; i++) {
            int r = v0 + r0 + i;
            if (r < nv) {
                float4 o = make_float4(acc[i][0], acc[i][1], acc[i][2], acc[i][3]);
                *(float4*)&outp[r * ostride + dbase + d0] = o;
            }
        }
    }
}

// ----------------------------------------------------------------
// K1b: per (b,s): f_proj = feat @ Wt4^T + bt; then for each context l:
//   cw = ba + sum_d Wa[d] * tanh(Tn_s[si][d] + Tn_e[ei][d] + Tp[pi][d] + f_proj[d])
// ----------------------------------------------------------------
__global__ void __launch_bounds__(256, 4)
k1b_cw(const float* __restrict__ x,
       const float* __restrict__ Wt,
       const float* __restrict__ bt,
       const float* __restrict__ Wa,
       const float* __restrict__ ba)
{
    __shared__ int si[LL], pi[LL], ei[LL];
    __shared__ float fproj[DD], was[DD];
    __shared__ float feat_s[FEAT];

    const int bs = blockIdx.x;
    const int b = bs / SS, s = bs % SS;
    const int t = threadIdx.x;

    if (t < LL) {
        int xb = bs * DD + FEAT + 3 * t;
        si[t] = (int)x[xb];
        pi[t] = (int)x[xb + 1];
        ei[t] = (int)x[xb + 2];
    }
    if (t < FEAT) feat_s[t] = x[bs * DD + t];
    __syncthreads();

    for (int d = t; d < DD; d += 256) {
        float acc = bt[d];
        const float* wrow = &Wt[d * DD + 300];
#pragma unroll
        for (int k = 0; k < FEAT; k++) acc += feat_s[k] * wrow[k];
        fproj[d] = acc;
        was[d] = Wa[d];
    }
    __syncthreads();

    const int warp = t >> 5, lane = t & 31;
    const float bav = ba[0];
    for (int l = warp; l < LL; l += 8) {
        const float* pn = &g_Tn[si[l] * 640];
        const float* pe = &g_Tn[ei[l] * 640 + 320];
        const float* pp = &g_Tp[pi[l] * 320];
        float sum = 0.f;
#pragma unroll
        for (int d = lane; d < DD; d += 32) {
            float v = pn[d] + pe[d] + pp[d] + fproj[d];
            sum += was[d] * tanhf(v);
        }
#pragma unroll
        for (int off = 16; off; off >>= 1) sum += __shfl_xor_sync(~0u, sum, off);
        if (lane == 0)
            g_cw[(b * LL + l) * SS + s] = sum + bav;
    }
}

// ----------------------------------------------------------------
// K2: softmax over s (axis=1) for each (b,l); write aw in [b][s][l]
// ----------------------------------------------------------------
__global__ void k2_softmax() {
    const int bl = blockIdx.x;     // b*100 + l
    const int t  = threadIdx.x;    // 128 threads
    const float* row = g_cw + bl * SS;
    float v0 = (t < SS) ? row[t] : -3.0e38f;

    __shared__ float sw[4];
    float v = v0;
#pragma unroll
    for (int off = 16; off; off >>= 1) v = fmaxf(v, __shfl_xor_sync(~0u, v, off));
    if ((t & 31) == 0) sw[t >> 5] = v;
    __syncthreads();
    float mx = fmaxf(fmaxf(sw[0], sw[1]), fmaxf(sw[2], sw[3]));
    __syncthreads();

    float e = (t < SS) ? expf(v0 - mx) : 0.f;
    float sv = e;
#pragma unroll
    for (int off = 16; off; off >>= 1) sv += __shfl_xor_sync(~0u, sv, off);
    if ((t & 31) == 0) sw[t >> 5] = sv;
    __syncthreads();
    float tot = sw[0] + sw[1] + sw[2] + sw[3];

    if (t < SS) {
        int b = bl / LL, l = bl % LL;
        g_aw[(b * SS + t) * LL + l] = e / tot;   // s = t
    }
}

// ----------------------------------------------------------------
// K3: code_vec via re-gather; build rnn_in = [feat(20), code_vec(320)]
// ----------------------------------------------------------------
__global__ void k3_codevec(const float* __restrict__ x,
                           const float* __restrict__ etab_n,
                           const float* __restrict__ etab_p)
{
    __shared__ float aw_s[LL];
    __shared__ int si[LL], pi[LL], ei[LL];
    __shared__ float awsum_s;
    const int bs = blockIdx.x;
    const int t  = threadIdx.x;   // 128

    if (t < LL) {
        aw_s[t] = g_aw[bs * LL + t];
        int xb = bs * DD + FEAT + 3 * t;
        si[t] = (int)x[xb];
        pi[t] = (int)x[xb + 1];
        ei[t] = (int)x[xb + 2];
    }
    __syncthreads();
    if (t == 0) {
        float a = 0.f;
        for (int l = 0; l < LL; l++) a += aw_s[l];
        awsum_s = a;
    }
    __syncthreads();

    float* outrow = g_rnn + bs * RNNIN;
    for (int j = t; j < RNNIN; j += 128) {
        float v;
        if (j < FEAT) {
            v = x[bs * DD + j];
        } else {
            int k = j - FEAT;
            float acc = 0.f;
            if (k < EMB) {
                for (int l = 0; l < LL; l++) acc += etab_n[si[l] * EMB + k] * aw_s[l];
            } else if (k < 2 * EMB) {
                int km = k - EMB;
                for (int l = 0; l < LL; l++) acc += etab_n[ei[l] * EMB + km] * aw_s[l];
            } else if (k < 3 * EMB) {
                int km = k - 2 * EMB;
                for (int l = 0; l < LL; l++) acc += etab_p[pi[l] * EMB + km] * aw_s[l];
            } else {
                acc = x[bs * DD + (k - 3 * EMB)] * awsum_s;
            }
            v = acc;
        }
        outrow[j] = v;
    }
}

// ----------------------------------------------------------------
// K4: x-part gates: g_gx = rnn_in @ W_ih^T + b_ih + b_hh
// CTA = 16 rows x 512 cols
// ----------------------------------------------------------------
__global__ void __launch_bounds__(512)
k4_gates(const float* __restrict__ bih, const float* __restrict__ bhh)
{
    __shared__ float A_s[16 * RNNIN];
    const int n  = threadIdx.x;        // gate column
    const int r0 = blockIdx.x * 16;

    for (int e = n; e < 16 * RNNIN; e += 512)
        A_s[e] = g_rnn[r0 * RNNIN + e];
    __syncthreads();

    float acc[16];
#pragma unroll
    for (int i = 0; i < 16; i++) acc[i] = 0.f;

#pragma unroll 4
    for (int k = 0; k < RNNIN; k++) {
        float w = g_WihT[k * G4 + n];
#pragma unroll
        for (int i = 0; i < 16; i++)
            acc[i] += A_s[i * RNNIN + k] * w;
    }
    float bias = bih[n] + bhh[n];
#pragma unroll
    for (int i = 0; i < 16; i++)
        g_gx[(r0 + i) * G4 + n] = acc[i] + bias;
}

// ----------------------------------------------------------------
// K5: LSTM recurrence. One CTA per batch element, 512 threads.
// ----------------------------------------------------------------
__global__ void __launch_bounds__(512)
k5_lstm()
{
    __shared__ float h_s[HID];
    __shared__ float gs[G4];
    const int b = blockIdx.x;
    const int n = threadIdx.x;

    if (n < HID) h_s[n] = 0.f;
    float c = 0.f;
    __syncthreads();

    for (int s = 0; s < SS; s++) {
        float acc = g_gx[(b * SS + s) * G4 + n];
#pragma unroll 16
        for (int k = 0; k < HID; k++)
            acc += g_WhhT[k * G4 + n] * h_s[k];
        gs[n] = acc;
        __syncthreads();
        if (n < HID) {
            float gi = gs[n];
            float gf = gs[HID + n];
            float gg = gs[2 * HID + n];
            float go = gs[3 * HID + n];
            c = sigf(gf) * c + sigf(gi) * tanhf(gg);
            float h = sigf(go) * tanhf(c);
            h_s[n] = h;
            g_hs[(b * SS + s) * HID + n] = h;
        }
        __syncthreads();
    }
}

// ----------------------------------------------------------------
// K6: out = sigmoid(hs @ W_fc^T + b_fc)
// ----------------------------------------------------------------
__global__ void k6_fc(const float* __restrict__ Wfc,
                      const float* __restrict__ bfc,
                      float* __restrict__ out)
{
    int t = blockIdx.x * blockDim.x + threadIdx.x;
    if (t >= BB * SS * NOUT) return;
    int bs = t / NOUT;
    int o  = t % NOUT;
    const float* hrow = g_hs + bs * HID;
    const float* wrow = Wfc + o * HID;
    float acc = bfc[o];
#pragma unroll 8
    for (int u = 0; u < HID; u++) acc += hrow[u] * wrow[u];
    out[t] = sigf(acc);
}

// ----------------------------------------------------------------
extern "C" void kernel_launch(void* const* d_in, const int* in_sizes, int n_in,
                              void* d_out, int out_size)
{
    const float* x      = (const float*)d_in[0];
    const float* etab_n = (const float*)d_in[1];
    const float* etab_p = (const float*)d_in[2];
    const float* Wt     = (const float*)d_in[3];
    const float* bt     = (const float*)d_in[4];
    const float* Wa     = (const float*)d_in[5];
    const float* ba     = (const float*)d_in[6];
    const float* Wih    = (const float*)d_in[7];
    const float* Whh    = (const float*)d_in[8];
    const float* bih    = (const float*)d_in[9];
    const float* bhh    = (const float*)d_in[10];
    const float* Wfc    = (const float*)d_in[11];
    const float* bfc    = (const float*)d_in[12];
    float* out = (float*)d_out;

    const int kp_smem = (128 * AS_STRIDE + 100 * WS_STRIDE) * 4;
    cudaFuncSetAttribute(kp_project, cudaFuncAttributeMaxDynamicSharedMemorySize, kp_smem);

    {
        int total = RNNIN * G4;
        k0_transpose<<<(total + 255) / 256, 256>>>(Wih, Whh);
    }
    kp_project<<<PROJ_NODE_BLOCKS + PROJ_PATH_BLOCKS, 256, kp_smem>>>(etab_n, etab_p, Wt);
    k1b_cw<<<BB * SS, 256>>>(x, Wt, bt, Wa, ba);
    k2_softmax<<<BB * LL, 128>>>();
    k3_codevec<<<BB * SS, 128>>>(x, etab_n, etab_p);
    k4_gates<<<BB * SS / 16, 512>>>(bih, bhh);
    k5_lstm<<<BB, 512>>>();
    {
        int total = BB * SS * NOUT;
        k6_fc<<<(total + 255) / 256, 256>>>(Wfc, bfc, out);
    }
}